// round 1
// baseline (speedup 1.0000x reference)
#include <cuda_runtime.h>
#include <cstdint>

// Problem constants
#define BATCH 4
#define C_IN  64
#define O_OUT 64
#define H_DIM 128
#define W_DIM 128

// Tiling
#define TH 16          // tile height
#define TW 16          // tile width
#define CH 8           // channels per smem stage
#define OPT 16         // output channels per block (4 o-groups)
#define NTHREADS 128   // 16 rows x 8 col-pairs

typedef unsigned long long ull;

__device__ __forceinline__ ull pack2(float lo, float hi) {
    ull r;
    asm("mov.b64 %0, {%1, %2};" : "=l"(r) : "f"(lo), "f"(hi));
    return r;
}
__device__ __forceinline__ void unpack2(ull v, float& lo, float& hi) {
    asm("mov.b64 {%0, %1}, %2;" : "=f"(lo), "=f"(hi) : "l"(v));
}
__device__ __forceinline__ ull fma2(ull a, ull b, ull c) {
    ull d;
    asm("fma.rn.f32x2 %0, %1, %2, %3;" : "=l"(d) : "l"(a), "l"(b), "l"(c));
    return d;
}

__global__ __launch_bounds__(NTHREADS)
void ConvSquare_kernel(const float* __restrict__ x,
                       const float* __restrict__ alpha,
                       const float* __restrict__ wgt,
                       const float* __restrict__ bias,
                       const float* __restrict__ pa,
                       const float* __restrict__ pb,
                       const float* __restrict__ pc,
                       float* __restrict__ out)
{
    // Shared: staged input halo tile (CH channels) + repacked weights [tap][c][o]
    __shared__ __align__(16) float xs[CH][TH + 2][TW + 3];   // 19-col stride (pad)
    __shared__ __align__(16) float ws[9][CH][OPT];           // o contiguous -> LDS.128 pairs

    const int bx = blockIdx.x;           // 0..7  (w tiles)
    const int by = blockIdx.y;           // 0..7  (h tiles)
    const int bz = blockIdx.z;           // batch*4 + ogroup
    const int batch = bz >> 2;
    const int obase = (bz & 3) * OPT;

    const int tid = threadIdx.x;
    const int pp  = tid & 7;             // col-pair index (0..7)
    const int py  = tid >> 3;            // tile row (0..15)
    const int w0  = bx * TW + 2 * pp;    // global w of pixel 0 (pixel 1 = w0+1)
    const int h   = by * TH + py;        // global h

    const float ka = *pa, kb = *pb, kc = *pc;

    // ---- Precompute f(alpha) for the 3x4 halo window of the 2 pixels (once) ----
    float fav[3][4];
    const float* arow = alpha + batch * H_DIM * W_DIM;
    #pragma unroll
    for (int i = 0; i < 3; i++) {
        const int gy = h - 1 + i;
        #pragma unroll
        for (int j = 0; j < 4; j++) {
            const int gx = w0 - 1 + j;
            float av = 0.f;
            if (gy >= 0 && gy < H_DIM && gx >= 0 && gx < W_DIM)
                av = arow[gy * W_DIM + gx];
            fav[i][j] = (ka * av + kb) * av + kc;
        }
    }

    // Accumulators: [pixel][o-pair] packed f32x2 over (o, o+1)
    ull acc[2][OPT / 2];
    #pragma unroll
    for (int p = 0; p < 2; p++)
        #pragma unroll
        for (int k = 0; k < OPT / 2; k++)
            acc[p][k] = 0ull;

    const int px0 = 2 * pp;  // tile-local halo col base for this thread

    for (int c0 = 0; c0 < C_IN; c0 += CH) {
        // ---- Stage input halo tile (CH channels) ----
        for (int idx = tid; idx < CH * 18 * 18; idx += NTHREADS) {
            const int cc  = idx / (18 * 18);
            const int r   = idx % (18 * 18);
            const int row = r / 18;
            const int col = r % 18;
            const int gy  = by * TH + row - 1;
            const int gx  = bx * TW + col - 1;
            float v = 0.f;
            if (gy >= 0 && gy < H_DIM && gx >= 0 && gx < W_DIM)
                v = x[((batch * C_IN + c0 + cc) * H_DIM + gy) * W_DIM + gx];
            xs[cc][row][col] = v;
        }
        // ---- Stage weights repacked as [tap][c][o] ----
        for (int idx = tid; idx < 9 * CH * OPT; idx += NTHREADS) {
            const int tap = idx / (CH * OPT);
            const int r   = idx % (CH * OPT);
            const int cc  = r / OPT;
            const int ol  = r % OPT;
            ws[tap][cc][ol] = wgt[(obase + ol) * (C_IN * 9) + (c0 + cc) * 9 + tap];
        }
        __syncthreads();

        #pragma unroll 4
        for (int cc = 0; cc < CH; cc++) {
            // 3x4 input window covers both pixels' 3x3 windows
            float xr[3][4];
            #pragma unroll
            for (int i = 0; i < 3; i++)
                #pragma unroll
                for (int j = 0; j < 4; j++)
                    xr[i][j] = xs[cc][py + i][px0 + j];

            #pragma unroll
            for (int i = 0; i < 3; i++) {
                #pragma unroll
                for (int j = 0; j < 3; j++) {
                    const int tap = i * 3 + j;
                    const float p0 = xr[i][j]     * fav[i][j];
                    const float p1 = xr[i][j + 1] * fav[i][j + 1];
                    const ull P0 = pack2(p0, p0);
                    const ull P1 = pack2(p1, p1);
                    const ulonglong2* wp =
                        reinterpret_cast<const ulonglong2*>(&ws[tap][cc][0]);
                    #pragma unroll
                    for (int k = 0; k < 4; k++) {   // 4 x LDS.128 = 8 f32x2 W pairs
                        const ulonglong2 wv = wp[k];
                        acc[0][2 * k]     = fma2(P0, wv.x, acc[0][2 * k]);
                        acc[0][2 * k + 1] = fma2(P0, wv.y, acc[0][2 * k + 1]);
                        acc[1][2 * k]     = fma2(P1, wv.x, acc[1][2 * k]);
                        acc[1][2 * k + 1] = fma2(P1, wv.y, acc[1][2 * k + 1]);
                    }
                }
            }
        }
        __syncthreads();
    }

    // ---- Epilogue: add bias, store as float2 over the adjacent-w pixel pair ----
    float* outp = out + ((size_t)(batch * O_OUT + obase) * H_DIM + h) * W_DIM + w0;
    #pragma unroll
    for (int kp = 0; kp < OPT / 2; kp++) {
        float a0lo, a0hi, a1lo, a1hi;
        unpack2(acc[0][kp], a0lo, a0hi);   // pixel0: (o_even, o_odd)
        unpack2(acc[1][kp], a1lo, a1hi);   // pixel1
        const float b0 = bias[obase + 2 * kp];
        const float b1 = bias[obase + 2 * kp + 1];
        float2 v0 = make_float2(a0lo + b0, a1lo + b0);
        float2 v1 = make_float2(a0hi + b1, a1hi + b1);
        *reinterpret_cast<float2*>(outp + (size_t)(2 * kp)     * H_DIM * W_DIM) = v0;
        *reinterpret_cast<float2*>(outp + (size_t)(2 * kp + 1) * H_DIM * W_DIM) = v1;
    }
}

extern "C" void kernel_launch(void* const* d_in, const int* in_sizes, int n_in,
                              void* d_out, int out_size)
{
    const float* x     = (const float*)d_in[0];  // [4,64,128,128]
    const float* alpha = (const float*)d_in[1];  // [4,1,128,128]
    const float* wgt   = (const float*)d_in[2];  // [64,64,3,3]
    const float* bias  = (const float*)d_in[3];  // [64]
    const float* pa    = (const float*)d_in[4];  // scalar
    const float* pb    = (const float*)d_in[5];  // scalar
    const float* pc    = (const float*)d_in[6];  // scalar
    float* out = (float*)d_out;                  // [4,64,128,128]

    dim3 grid(W_DIM / TW, H_DIM / TH, BATCH * (O_OUT / OPT));  // (8, 8, 16)
    ConvSquare_kernel<<<grid, NTHREADS>>>(x, alpha, wgt, bias, pa, pb, pc, out);
}